// round 3
// baseline (speedup 1.0000x reference)
#include <cuda_runtime.h>

#define N0        32768
#define NTHREADS  1024

// DEC_LO (db4 lowpass)
#define D0 (-0.010597401784997278f)
#define D1 ( 0.032883011666982945f)
#define D2 ( 0.030841381835986965f)
#define D3 (-0.18703481171888114f)
#define D4 (-0.02798376941698385f)
#define D5 ( 0.6308807679295904f)
#define D6 ( 0.7148465705525415f)
#define D7 ( 0.23037781330885523f)

// Analysis filter h = reverse(DEC_LO); synthesis g = DEC_LO
#define H0 D7
#define H1 D6
#define H2 D5
#define H3 D4
#define H4 D3
#define H5 D2
#define H6 D1
#define H7 D0

// SMEM layout (in floats):
//  [0,8)                      x front guard
//  [8, 8+32768)               x data
//  [8+32768, 8+32768+8)       x back guard
//  B region: front guard 8, data cap 16388, back guard 8
//  A region: front guard 8, data cap  8198, back guard 8
#define XS_OFF   8
#define B_OFF    (8 + N0 + 8 + 8)                 // 32792
#define A_OFF    (B_OFF + 16388 + 8 + 8)          // 49196
#define SMEM_FLOATS (A_OFF + 8198 + 8)            // 57402
#define SMEM_BYTES  (SMEM_FLOATS * 4)             // 229608

// analysis: out[n] = sum_l h[l] * in[2n-6+l], guards supply zeros outside
__device__ __forceinline__ void analysis_stage(const float* __restrict__ in,
                                               float* __restrict__ dst,
                                               int outsize) {
    for (int n = threadIdx.x; n < outsize; n += NTHREADS) {
        const float* p = in + 2 * n - 6;
        float acc = H0 * p[0];
        acc = fmaf(H1, p[1], acc);
        acc = fmaf(H2, p[2], acc);
        acc = fmaf(H3, p[3], acc);
        acc = fmaf(H4, p[4], acc);
        acc = fmaf(H5, p[5], acc);
        acc = fmaf(H6, p[6], acc);
        acc = fmaf(H7, p[7], acc);
        dst[n] = acc;
    }
    // zero guards of dst for the NEXT analysis stage (reads up to outsize+6)
    if (threadIdx.x < 8) {
        dst[(int)threadIdx.x - 8] = 0.0f;
        dst[outsize + (int)threadIdx.x] = 0.0f;
    }
}

// synthesis: out[2m]   = g1*lo[m] + g3*lo[m+1] + g5*lo[m+2] + g7*lo[m+3]
//            out[2m+1] = g0*lo[m] + g2*lo[m+1] + g4*lo[m+2] + g6*lo[m+3]
// m in [0, Nlo-3); out length = 2*Nlo - 6. No bounds checks needed.
__device__ __forceinline__ void synthesis_stage(const float* __restrict__ lo,
                                                float* __restrict__ dst,
                                                int Nlo) {
    const int P = Nlo - 3;
    for (int m = threadIdx.x; m < P; m += NTHREADS) {
        float l0 = lo[m];
        float l1 = lo[m + 1];
        float l2 = lo[m + 2];
        float l3 = lo[m + 3];
        float e = D1 * l0;
        e = fmaf(D3, l1, e); e = fmaf(D5, l2, e); e = fmaf(D7, l3, e);
        float o = D0 * l0;
        o = fmaf(D2, l1, o); o = fmaf(D4, l2, o); o = fmaf(D6, l3, o);
        *reinterpret_cast<float2*>(dst + 2 * m) = make_float2(e, o);
    }
}

__global__ void __launch_bounds__(NTHREADS, 1)
wt_decomp_kernel(const float* __restrict__ x, float* __restrict__ out, int rows) {
    extern __shared__ float smem[];
    float* xs = smem + XS_OFF;
    float* B  = smem + B_OFF;
    float* A  = smem + A_OFF;

    const int row = blockIdx.x;
    const float* xrow = x + (size_t)row * N0;

    // Load x row into smem (coalesced float4), zero guards
    {
        float4* xs4 = reinterpret_cast<float4*>(xs);
        const float4* xg4 = reinterpret_cast<const float4*>(xrow);
        for (int i = threadIdx.x; i < N0 / 4; i += NTHREADS) xs4[i] = xg4[i];
        if (threadIdx.x < 8) {
            xs[(int)threadIdx.x - 8] = 0.0f;
            xs[N0 + (int)threadIdx.x] = 0.0f;
        }
    }
    __syncthreads();

    // Analysis pyramid: 32768 -> 16387 -> 8197 -> 4102 -> 2054
    analysis_stage(xs, B, 16387);  __syncthreads();
    analysis_stage(B,  A, 8197);   __syncthreads();
    analysis_stage(A,  B, 4102);   __syncthreads();
    analysis_stage(B,  A, 2054);   __syncthreads();

    // Synthesis: 2054 -> 4102 -> 8198 -> (trim 8197) -> 16388 -> (trim 16387) -> 32768
    synthesis_stage(A, B, 2054);   __syncthreads();  // t1: 4102 in B
    synthesis_stage(B, A, 4102);   __syncthreads();  // t2: 8198 in A
    synthesis_stage(A, B, 8197);   __syncthreads();  // t3: 16388 in B (trimmed input)

    // Final synthesis (Nlo = 16387 after trim) fused with season = x - trend,
    // streamed straight to global. 16384 pairs -> 32768 outputs.
    float* season = out + (size_t)row * N0;
    float* trend  = out + (size_t)rows * N0 + (size_t)row * N0;
    float2* season2 = reinterpret_cast<float2*>(season);
    float2* trend2  = reinterpret_cast<float2*>(trend);
    const float2* xs2 = reinterpret_cast<const float2*>(xs);

    for (int m = threadIdx.x; m < 16384; m += NTHREADS) {
        float l0 = B[m];
        float l1 = B[m + 1];
        float l2 = B[m + 2];
        float l3 = B[m + 3];
        float te = D1 * l0;
        te = fmaf(D3, l1, te); te = fmaf(D5, l2, te); te = fmaf(D7, l3, te);
        float to = D0 * l0;
        to = fmaf(D2, l1, to); to = fmaf(D4, l2, to); to = fmaf(D6, l3, to);
        float2 xv = xs2[m];
        trend2[m]  = make_float2(te, to);
        season2[m] = make_float2(xv.x - te, xv.y - to);
    }
}

extern "C" void kernel_launch(void* const* d_in, const int* in_sizes, int n_in,
                              void* d_out, int out_size) {
    const float* x = (const float*)d_in[0];
    float* out = (float*)d_out;
    const int rows = in_sizes[0] / N0;  // 32 * 16 = 512

    static bool attr_set = false;
    if (!attr_set) {
        cudaFuncSetAttribute(wt_decomp_kernel,
                             cudaFuncAttributeMaxDynamicSharedMemorySize, SMEM_BYTES);
        attr_set = true;
    }
    wt_decomp_kernel<<<rows, NTHREADS, SMEM_BYTES>>>(x, out, rows);
}

// round 4
// speedup vs baseline: 1.0581x; 1.0581x over previous
#include <cuda_runtime.h>

#define N0        32768
#define NTHREADS  1024

// DEC_LO (db4 lowpass)
#define D0 (-0.010597401784997278f)
#define D1 ( 0.032883011666982945f)
#define D2 ( 0.030841381835986965f)
#define D3 (-0.18703481171888114f)
#define D4 (-0.02798376941698385f)
#define D5 ( 0.6308807679295904f)
#define D6 ( 0.7148465705525415f)
#define D7 ( 0.23037781330885523f)

// Analysis filter h = reverse(DEC_LO); synthesis g = DEC_LO
#define H0 D7
#define H1 D6
#define H2 D5
#define H3 D4
#define H4 D3
#define H5 D2
#define H6 D1
#define H7 D0

// SMEM layout (in floats):
//  [0,8)                      x front guard
//  [8, 8+32768)               x data
//  [8+32768, 8+32768+8)       x back guard
//  B region: front guard 8, data cap 16388, back guard 8
//  A region: front guard 8, data cap  8198, back guard 8
// All region bases are even float offsets -> (base + 2n-6)*4 is 8B-aligned.
#define XS_OFF   8
#define B_OFF    (8 + N0 + 8 + 8)                 // 32792
#define A_OFF    (B_OFF + 16388 + 8 + 8)          // 49196
#define SMEM_FLOATS (A_OFF + 8198 + 8)            // 57402
#define SMEM_BYTES  (SMEM_FLOATS * 4)             // 229608

// analysis: out[n] = sum_l h[l] * in[2n-6+l], guards supply zeros outside.
// Reads via float2 (LDS.64): lane stride 8B -> dense, bank-conflict-free
// (vs the stride-2 LDS.32 version which is 2-way conflicted on every load).
__device__ __forceinline__ void analysis_stage(const float* __restrict__ in,
                                               float* __restrict__ dst,
                                               int outsize) {
#pragma unroll 2
    for (int n = threadIdx.x; n < outsize; n += NTHREADS) {
        const float2* p2 = reinterpret_cast<const float2*>(in + 2 * n - 6);
        float2 v0 = p2[0];
        float2 v1 = p2[1];
        float2 v2 = p2[2];
        float2 v3 = p2[3];
        float acc = H0 * v0.x;
        acc = fmaf(H1, v0.y, acc);
        acc = fmaf(H2, v1.x, acc);
        acc = fmaf(H3, v1.y, acc);
        acc = fmaf(H4, v2.x, acc);
        acc = fmaf(H5, v2.y, acc);
        acc = fmaf(H6, v3.x, acc);
        acc = fmaf(H7, v3.y, acc);
        dst[n] = acc;
    }
    // zero guards of dst for the NEXT analysis stage (reads up to outsize+7)
    if (threadIdx.x < 8) {
        dst[(int)threadIdx.x - 8] = 0.0f;
        dst[outsize + (int)threadIdx.x] = 0.0f;
    }
}

// synthesis: out[2m]   = g1*lo[m] + g3*lo[m+1] + g5*lo[m+2] + g7*lo[m+3]
//            out[2m+1] = g0*lo[m] + g2*lo[m+1] + g4*lo[m+2] + g6*lo[m+3]
// m in [0, Nlo-3); out length = 2*Nlo - 6. Reads are unit-stride (no conflicts),
// writes are dense STS.64. No bounds checks needed.
__device__ __forceinline__ void synthesis_stage(const float* __restrict__ lo,
                                                float* __restrict__ dst,
                                                int Nlo) {
    const int P = Nlo - 3;
#pragma unroll 2
    for (int m = threadIdx.x; m < P; m += NTHREADS) {
        float l0 = lo[m];
        float l1 = lo[m + 1];
        float l2 = lo[m + 2];
        float l3 = lo[m + 3];
        float e = D1 * l0;
        e = fmaf(D3, l1, e); e = fmaf(D5, l2, e); e = fmaf(D7, l3, e);
        float o = D0 * l0;
        o = fmaf(D2, l1, o); o = fmaf(D4, l2, o); o = fmaf(D6, l3, o);
        *reinterpret_cast<float2*>(dst + 2 * m) = make_float2(e, o);
    }
}

__global__ void __launch_bounds__(NTHREADS, 1)
wt_decomp_kernel(const float* __restrict__ x, float* __restrict__ out, int rows) {
    extern __shared__ float smem[];
    float* xs = smem + XS_OFF;
    float* B  = smem + B_OFF;
    float* A  = smem + A_OFF;

    const int row = blockIdx.x;
    const float* xrow = x + (size_t)row * N0;

    // Load x row into smem (coalesced float4), zero guards
    {
        float4* xs4 = reinterpret_cast<float4*>(xs);
        const float4* xg4 = reinterpret_cast<const float4*>(xrow);
#pragma unroll 2
        for (int i = threadIdx.x; i < N0 / 4; i += NTHREADS) xs4[i] = xg4[i];
        if (threadIdx.x < 8) {
            xs[(int)threadIdx.x - 8] = 0.0f;
            xs[N0 + (int)threadIdx.x] = 0.0f;
        }
    }
    __syncthreads();

    // Analysis pyramid: 32768 -> 16387 -> 8197 -> 4102 -> 2054
    analysis_stage(xs, B, 16387);  __syncthreads();
    analysis_stage(B,  A, 8197);   __syncthreads();
    analysis_stage(A,  B, 4102);   __syncthreads();
    analysis_stage(B,  A, 2054);   __syncthreads();

    // Synthesis: 2054 -> 4102 -> 8198 -> (trim 8197) -> 16388 -> (trim 16387) -> 32768
    synthesis_stage(A, B, 2054);   __syncthreads();  // t1: 4102 in B
    synthesis_stage(B, A, 4102);   __syncthreads();  // t2: 8198 in A
    synthesis_stage(A, B, 8197);   __syncthreads();  // t3: 16388 in B (trimmed input)

    // Final synthesis (Nlo = 16387 after trim) fused with season = x - trend,
    // streamed straight to global. 16384 pairs -> 32768 outputs.
    float* season = out + (size_t)row * N0;
    float* trend  = out + (size_t)rows * N0 + (size_t)row * N0;
    float2* season2 = reinterpret_cast<float2*>(season);
    float2* trend2  = reinterpret_cast<float2*>(trend);
    const float2* xs2 = reinterpret_cast<const float2*>(xs);

#pragma unroll 2
    for (int m = threadIdx.x; m < 16384; m += NTHREADS) {
        float l0 = B[m];
        float l1 = B[m + 1];
        float l2 = B[m + 2];
        float l3 = B[m + 3];
        float te = D1 * l0;
        te = fmaf(D3, l1, te); te = fmaf(D5, l2, te); te = fmaf(D7, l3, te);
        float to = D0 * l0;
        to = fmaf(D2, l1, to); to = fmaf(D4, l2, to); to = fmaf(D6, l3, to);
        float2 xv = xs2[m];
        trend2[m]  = make_float2(te, to);
        season2[m] = make_float2(xv.x - te, xv.y - to);
    }
}

extern "C" void kernel_launch(void* const* d_in, const int* in_sizes, int n_in,
                              void* d_out, int out_size) {
    const float* x = (const float*)d_in[0];
    float* out = (float*)d_out;
    const int rows = in_sizes[0] / N0;  // 32 * 16 = 512

    static bool attr_set = false;
    if (!attr_set) {
        cudaFuncSetAttribute(wt_decomp_kernel,
                             cudaFuncAttributeMaxDynamicSharedMemorySize, SMEM_BYTES);
        attr_set = true;
    }
    wt_decomp_kernel<<<rows, NTHREADS, SMEM_BYTES>>>(x, out, rows);
}

// round 6
// speedup vs baseline: 1.1557x; 1.0922x over previous
#include <cuda_runtime.h>

#define N0        32768
#define NTHREADS  1024

// DEC_LO (db4 lowpass)
#define D0 (-0.010597401784997278f)
#define D1 ( 0.032883011666982945f)
#define D2 ( 0.030841381835986965f)
#define D3 (-0.18703481171888114f)
#define D4 (-0.02798376941698385f)
#define D5 ( 0.6308807679295904f)
#define D6 ( 0.7148465705525415f)
#define D7 ( 0.23037781330885523f)

// Analysis filter h = reverse(DEC_LO); synthesis g = DEC_LO
#define H0 D7
#define H1 D6
#define H2 D5
#define H3 D4
#define H4 D3
#define H5 D2
#define H6 D1
#define H7 D0

// SMEM layout (floats). x is NOT kept in smem (read from global in stage 1
// and in the fused final stage) -> smem is only the two ping-pong buffers
// -> 98.5 KB -> 2 CTAs/SM.
//  B region: front guard 8, data cap 16388, back guard 8
//  A region: front guard 8, data cap  8198, back guard 8
#define B_OFF    8
#define A_OFF    (8 + 16388 + 8 + 8)              // 16412
#define SMEM_FLOATS (A_OFF + 8198 + 8)            // 24618
#define SMEM_BYTES  (SMEM_FLOATS * 4)             // 98472

// smem->smem analysis: out[n] = sum_l h[l] * in[2n-6+l], guard zeros outside.
__device__ __forceinline__ void analysis_stage(const float* __restrict__ in,
                                               float* __restrict__ dst,
                                               int outsize) {
#pragma unroll 2
    for (int n = threadIdx.x; n < outsize; n += NTHREADS) {
        const float2* p2 = reinterpret_cast<const float2*>(in + 2 * n - 6);
        float2 v0 = p2[0];
        float2 v1 = p2[1];
        float2 v2 = p2[2];
        float2 v3 = p2[3];
        float acc = H0 * v0.x;
        acc = fmaf(H1, v0.y, acc);
        acc = fmaf(H2, v1.x, acc);
        acc = fmaf(H3, v1.y, acc);
        acc = fmaf(H4, v2.x, acc);
        acc = fmaf(H5, v2.y, acc);
        acc = fmaf(H6, v3.x, acc);
        acc = fmaf(H7, v3.y, acc);
        dst[n] = acc;
    }
    // zero guards of dst for the NEXT analysis stage (reads up to outsize+7)
    if (threadIdx.x < 8) {
        dst[(int)threadIdx.x - 8] = 0.0f;
        dst[outsize + (int)threadIdx.x] = 0.0f;
    }
}

// synthesis: out[2m]   = g1*lo[m] + g3*lo[m+1] + g5*lo[m+2] + g7*lo[m+3]
//            out[2m+1] = g0*lo[m] + g2*lo[m+1] + g4*lo[m+2] + g6*lo[m+3]
// m in [0, Nlo-3); out length = 2*Nlo - 6. No bounds checks needed.
__device__ __forceinline__ void synthesis_stage(const float* __restrict__ lo,
                                                float* __restrict__ dst,
                                                int Nlo) {
    const int P = Nlo - 3;
#pragma unroll 2
    for (int m = threadIdx.x; m < P; m += NTHREADS) {
        float l0 = lo[m];
        float l1 = lo[m + 1];
        float l2 = lo[m + 2];
        float l3 = lo[m + 3];
        float e = D1 * l0;
        e = fmaf(D3, l1, e); e = fmaf(D5, l2, e); e = fmaf(D7, l3, e);
        float o = D0 * l0;
        o = fmaf(D2, l1, o); o = fmaf(D4, l2, o); o = fmaf(D6, l3, o);
        *reinterpret_cast<float2*>(dst + 2 * m) = make_float2(e, o);
    }
}

__global__ void __launch_bounds__(NTHREADS, 2)
wt_decomp_kernel(const float* __restrict__ x, float* __restrict__ out, int rows) {
    extern __shared__ float smem[];
    float* B  = smem + B_OFF;
    float* A  = smem + A_OFF;

    const int row = blockIdx.x;
    const float* xrow = x + (size_t)row * N0;

    // ---- Analysis level 1: global x -> smem B (16387 outputs) ----
    // Body is unguarded (reads x[2n-6 .. 2n+1], valid for 3 <= n < 16383);
    // edges take a bounds-checked scalar path.
#pragma unroll 2
    for (int n = threadIdx.x; n < 16387; n += NTHREADS) {
        float acc;
        if (n >= 3 && n < 16383) {
            const float2* p2 = reinterpret_cast<const float2*>(xrow + 2 * n - 6);
            float2 v0 = p2[0];
            float2 v1 = p2[1];
            float2 v2 = p2[2];
            float2 v3 = p2[3];
            acc = H0 * v0.x;
            acc = fmaf(H1, v0.y, acc);
            acc = fmaf(H2, v1.x, acc);
            acc = fmaf(H3, v1.y, acc);
            acc = fmaf(H4, v2.x, acc);
            acc = fmaf(H5, v2.y, acc);
            acc = fmaf(H6, v3.x, acc);
            acc = fmaf(H7, v3.y, acc);
        } else {
            const float h[8] = {H0, H1, H2, H3, H4, H5, H6, H7};
            acc = 0.0f;
            const int base = 2 * n - 6;
#pragma unroll
            for (int l = 0; l < 8; l++) {
                int idx = base + l;
                float v = (idx >= 0 && idx < N0) ? xrow[idx] : 0.0f;
                acc = fmaf(h[l], v, acc);
            }
        }
        B[n] = acc;
    }
    if (threadIdx.x < 8) {
        B[(int)threadIdx.x - 8] = 0.0f;
        B[16387 + (int)threadIdx.x] = 0.0f;
    }
    __syncthreads();

    // Analysis pyramid (smem): 16387 -> 8197 -> 4102 -> 2054
    analysis_stage(B,  A, 8197);   __syncthreads();
    analysis_stage(A,  B, 4102);   __syncthreads();
    analysis_stage(B,  A, 2054);   __syncthreads();

    // Synthesis: 2054 -> 4102 -> 8198 -> (trim 8197) -> 16388 -> (trim 16387) -> 32768
    synthesis_stage(A, B, 2054);   __syncthreads();  // t1: 4102 in B
    synthesis_stage(B, A, 4102);   __syncthreads();  // t2: 8198 in A
    synthesis_stage(A, B, 8197);   __syncthreads();  // t3: 16388 in B (trimmed input)

    // Final synthesis (Nlo = 16387 after trim) fused with season = x - trend.
    // x re-read from global (L2-resident), outputs streamed to global.
    float* season = out + (size_t)row * N0;
    float* trend  = out + (size_t)rows * N0 + (size_t)row * N0;
    float2* season2 = reinterpret_cast<float2*>(season);
    float2* trend2  = reinterpret_cast<float2*>(trend);
    const float2* xg2 = reinterpret_cast<const float2*>(xrow);

#pragma unroll 2
    for (int m = threadIdx.x; m < 16384; m += NTHREADS) {
        float l0 = B[m];
        float l1 = B[m + 1];
        float l2 = B[m + 2];
        float l3 = B[m + 3];
        float te = D1 * l0;
        te = fmaf(D3, l1, te); te = fmaf(D5, l2, te); te = fmaf(D7, l3, te);
        float to = D0 * l0;
        to = fmaf(D2, l1, to); to = fmaf(D4, l2, to); to = fmaf(D6, l3, to);
        float2 xv = xg2[m];
        trend2[m]  = make_float2(te, to);
        season2[m] = make_float2(xv.x - te, xv.y - to);
    }
}

extern "C" void kernel_launch(void* const* d_in, const int* in_sizes, int n_in,
                              void* d_out, int out_size) {
    const float* x = (const float*)d_in[0];
    float* out = (float*)d_out;
    const int rows = in_sizes[0] / N0;  // 32 * 16 = 512

    static bool attr_set = false;
    if (!attr_set) {
        cudaFuncSetAttribute(wt_decomp_kernel,
                             cudaFuncAttributeMaxDynamicSharedMemorySize, SMEM_BYTES);
        attr_set = true;
    }
    wt_decomp_kernel<<<rows, NTHREADS, SMEM_BYTES>>>(x, out, rows);
}